// round 1
// baseline (speedup 1.0000x reference)
#include <cuda_runtime.h>
#include <math.h>

// ---------------- model constants ----------------
#define L_     2
#define HID_   4096
#define NH_    32
#define HD_    128
#define INTER_ 13696
#define B_     2
#define S_     1024
#define T_     2048
#define NBLK_  160
#define BLK_   16
#define ROT_   64
#define NFREQ_ 32
#define EPS_   1e-5f
#define SCALE_ 0.08838834764831845f   // HD^-0.5

// ---------------- scratch (device globals; no allocation) ----------------
#define OFF_H      ((size_t)0)
#define OFF_RES    ((size_t)8388608)
#define OFF_NORM   ((size_t)16777216)
#define OFF_Q      ((size_t)25165824)
#define OFF_K      ((size_t)33554432)
#define OFF_V      ((size_t)41943040)
#define OFF_O      ((size_t)50331648)
#define OFF_ATTN   ((size_t)58720256)
#define OFF_QKV    ((size_t)67108864)   // 25165824 floats
#define OFF_SCORES ((size_t)92274688)   // 67108864 floats
#define OFF_GU     ((size_t)159383552)  // 56098816 floats
#define OFF_ACT    ((size_t)215482368)  // 28049408 floats
#define SCRATCH_TOTAL ((size_t)243531776)

__device__ float g_scratch[SCRATCH_TOTAL];

// ---------------- embedding gather ----------------
__global__ void embed_kernel(const int* __restrict__ ids,
                             const float* __restrict__ E,
                             float* __restrict__ h) {
    int t = blockIdx.x;
    int id = ids[t];
    const float* er = E + (size_t)id * HID_;
    float* hr = h + (size_t)t * HID_;
    for (int i = threadIdx.x; i < HID_; i += 256) hr[i] = er[i];
}

// ---------------- fused (residual-add) RMSNorm ----------------
__global__ void rmsnorm_kernel(const float* __restrict__ x,
                               const float* __restrict__ resin,
                               const float* __restrict__ w,
                               float* __restrict__ outn,
                               float* __restrict__ resout) {
    int t = blockIdx.x, tid = threadIdx.x;
    const float* xr = x + (size_t)t * HID_;
    const float* rr = resin ? resin + (size_t)t * HID_ : nullptr;
    float* on = outn + (size_t)t * HID_;
    float* ro = resout ? resout + (size_t)t * HID_ : nullptr;

    float v[16];
    float ss = 0.f;
#pragma unroll
    for (int i = 0; i < 16; i++) {
        int c = tid + i * 256;
        float a = xr[c];
        if (rr) a += rr[c];
        v[i] = a;
        ss += a * a;
    }
    __shared__ float red[8];
#pragma unroll
    for (int o = 16; o; o >>= 1) ss += __shfl_xor_sync(0xffffffffu, ss, o);
    if ((tid & 31) == 0) red[tid >> 5] = ss;
    __syncthreads();
    float tot = 0.f;
#pragma unroll
    for (int i = 0; i < 8; i++) tot += red[i];
    float inv = rsqrtf(tot * (1.0f / HID_) + EPS_);
#pragma unroll
    for (int i = 0; i < 16; i++) {
        int c = tid + i * 256;
        if (ro) ro[c] = v[i];
        on[c] = w[c] * v[i] * inv;
    }
}

// ---------------- generic SGEMM: C = A(MxK) @ B(KxN) (+bias) ----------------
// lda=K, ldb=N, ldc=N. All dims divisible by tiles in our uses.
__global__ void __launch_bounds__(256) sgemm_nn(const float* __restrict__ A,
                                                const float* __restrict__ Bm,
                                                const float* __restrict__ bias,
                                                float* __restrict__ C,
                                                int M, int N, int K) {
    __shared__ float As[8][132];
    __shared__ float Bs[8][128];
    int bx = blockIdx.x, by = blockIdx.y;
    int tid = threadIdx.x;
    int tx = tid & 15, ty = tid >> 4;

    int aRow = tid >> 1;
    int aCol = (tid & 1) * 4;
    int bRow = tid >> 5;
    int bCol = (tid & 31) * 4;

    const float* Ap = A + (size_t)(by * 128 + aRow) * K + aCol;
    const float* Bp = Bm + (size_t)bRow * N + bx * 128 + bCol;

    float acc[8][8] = {};
    for (int k0 = 0; k0 < K; k0 += 8) {
        float4 a4 = *(const float4*)(Ap + k0);
        As[aCol + 0][aRow] = a4.x;
        As[aCol + 1][aRow] = a4.y;
        As[aCol + 2][aRow] = a4.z;
        As[aCol + 3][aRow] = a4.w;
        float4 b4 = *(const float4*)(Bp + (size_t)k0 * N);
        *(float4*)&Bs[bRow][bCol] = b4;
        __syncthreads();
#pragma unroll
        for (int kk = 0; kk < 8; kk++) {
            float ar[8], br[8];
#pragma unroll
            for (int i = 0; i < 8; i++) ar[i] = As[kk][ty * 8 + i];
#pragma unroll
            for (int j = 0; j < 8; j++) br[j] = Bs[kk][tx * 8 + j];
#pragma unroll
            for (int i = 0; i < 8; i++)
#pragma unroll
                for (int j = 0; j < 8; j++) acc[i][j] += ar[i] * br[j];
        }
        __syncthreads();
    }
#pragma unroll
    for (int i = 0; i < 8; i++) {
        int r = by * 128 + ty * 8 + i;
#pragma unroll
        for (int j = 0; j < 8; j++) {
            int c = bx * 128 + tx * 8 + j;
            float vv = acc[i][j];
            if (bias) vv += bias[c];
            C[(size_t)r * N + c] = vv;
        }
    }
}

// ---------------- rope + split + KV-cache scatter ----------------
// qkv: [T, 3*HID]; outputs q/k/v: [T, NH, HD]; caches laid out [slot, NH, HD].
__global__ void rope_scatter(const float* __restrict__ qkv,
                             const float* __restrict__ cosp,
                             const float* __restrict__ sinp,
                             const int* __restrict__ slots,
                             float* __restrict__ q, float* __restrict__ k,
                             float* __restrict__ v,
                             float* __restrict__ kc, float* __restrict__ vc) {
    int t = blockIdx.x, h = blockIdx.y, d = threadIdx.x;
    const float* row = qkv + (size_t)t * (3 * HID_);
    float qv, kv;
    if (d < ROT_) {
        int f = d >> 1;
        float c = cosp[t * NFREQ_ + f];
        float s = sinp[t * NFREQ_ + f];
        float q0 = row[h * HD_ + f * 2];
        float q1 = row[h * HD_ + f * 2 + 1];
        float k0 = row[HID_ + h * HD_ + f * 2];
        float k1 = row[HID_ + h * HD_ + f * 2 + 1];
        if (d & 1) {
            qv = q1 * c + q0 * s;
            kv = k1 * c + k0 * s;
        } else {
            qv = q0 * c - q1 * s;
            kv = k0 * c - k1 * s;
        }
    } else {
        qv = row[h * HD_ + d];
        kv = row[HID_ + h * HD_ + d];
    }
    float vv = row[2 * HID_ + h * HD_ + d];
    size_t o = (size_t)t * HID_ + h * HD_ + d;
    q[o] = qv;
    k[o] = kv;
    v[o] = vv;
    if (kc) {
        int slot = slots[t];
        size_t co = ((size_t)slot * NH_ + h) * HD_ + d;
        kc[co] = kv;
        vc[co] = vv;
    }
}

// ---------------- scores = scale * Q @ K^T (batched per b,h; causal tile skip) ---
__global__ void __launch_bounds__(256) scores_kernel(const float* __restrict__ Q,
                                                     const float* __restrict__ Km,
                                                     float* __restrict__ Sc) {
    int bx = blockIdx.x, by = blockIdx.y;
    if (bx > by) return;  // fully masked tile, never read by softmax
    int bz = blockIdx.z;
    int b = bz >> 5, h = bz & 31;
    const float* A = Q + ((size_t)b * S_) * HID_ + h * HD_;
    const float* Bm = Km + ((size_t)b * S_) * HID_ + h * HD_;
    float* C = Sc + (size_t)bz * S_ * S_;

    __shared__ float As[8][132];
    __shared__ float Bs[8][132];
    int tid = threadIdx.x;
    int tx = tid & 15, ty = tid >> 4;
    int aRow = tid >> 1;
    int aCol = (tid & 1) * 4;
    const float* Ap = A + (size_t)(by * 128 + aRow) * HID_ + aCol;
    const float* Bp = Bm + (size_t)(bx * 128 + aRow) * HID_ + aCol;

    float acc[8][8] = {};
    for (int k0 = 0; k0 < HD_; k0 += 8) {
        float4 a4 = *(const float4*)(Ap + k0);
        As[aCol + 0][aRow] = a4.x;
        As[aCol + 1][aRow] = a4.y;
        As[aCol + 2][aRow] = a4.z;
        As[aCol + 3][aRow] = a4.w;
        float4 b4 = *(const float4*)(Bp + k0);
        Bs[aCol + 0][aRow] = b4.x;
        Bs[aCol + 1][aRow] = b4.y;
        Bs[aCol + 2][aRow] = b4.z;
        Bs[aCol + 3][aRow] = b4.w;
        __syncthreads();
#pragma unroll
        for (int kk = 0; kk < 8; kk++) {
            float ar[8], br[8];
#pragma unroll
            for (int i = 0; i < 8; i++) ar[i] = As[kk][ty * 8 + i];
#pragma unroll
            for (int j = 0; j < 8; j++) br[j] = Bs[kk][tx * 8 + j];
#pragma unroll
            for (int i = 0; i < 8; i++)
#pragma unroll
                for (int j = 0; j < 8; j++) acc[i][j] += ar[i] * br[j];
        }
        __syncthreads();
    }
#pragma unroll
    for (int i = 0; i < 8; i++) {
        int r = by * 128 + ty * 8 + i;
#pragma unroll
        for (int j = 0; j < 8; j++) {
            int c = bx * 128 + tx * 8 + j;
            C[(size_t)r * S_ + c] = acc[i][j] * SCALE_;
        }
    }
}

// ---------------- causal softmax (in place, writes zeros above diagonal) ----
__global__ void softmax_causal(float* __restrict__ Sc) {
    int row = blockIdx.x;               // (b*NH + h)*S + qi
    int qi = row & (S_ - 1);
    float* sr = Sc + (size_t)row * S_;
    int n = qi + 1;
    int tid = threadIdx.x;
    __shared__ float red[8];

    float m = -1e30f;
    for (int k = tid; k < n; k += 256) m = fmaxf(m, sr[k]);
#pragma unroll
    for (int o = 16; o; o >>= 1) m = fmaxf(m, __shfl_xor_sync(0xffffffffu, m, o));
    if ((tid & 31) == 0) red[tid >> 5] = m;
    __syncthreads();
    float mm = red[0];
#pragma unroll
    for (int i = 1; i < 8; i++) mm = fmaxf(mm, red[i]);
    __syncthreads();

    float sum = 0.f;
    for (int k = tid; k < n; k += 256) {
        float e = expf(sr[k] - mm);
        sr[k] = e;
        sum += e;
    }
#pragma unroll
    for (int o = 16; o; o >>= 1) sum += __shfl_xor_sync(0xffffffffu, sum, o);
    if ((tid & 31) == 0) red[tid >> 5] = sum;
    __syncthreads();
    float tot = 0.f;
#pragma unroll
    for (int i = 0; i < 8; i++) tot += red[i];
    float inv = 1.f / tot;
    for (int k = tid; k < n; k += 256) sr[k] *= inv;
    for (int k = n + tid; k < S_; k += 256) sr[k] = 0.f;  // needed by PV K-limit tiles
}

// ---------------- O = P @ V (batched; causal K-limit per q tile) ----------------
__global__ void __launch_bounds__(256) attn_o_kernel(const float* __restrict__ P,
                                                     const float* __restrict__ V,
                                                     float* __restrict__ O) {
    int by = blockIdx.y;
    int bz = blockIdx.z;
    int b = bz >> 5, h = bz & 31;
    const float* A = P + (size_t)bz * S_ * S_;                 // lda = S
    const float* Bm = V + ((size_t)b * S_) * HID_ + h * HD_;   // row stride HID
    float* C = O + ((size_t)b * S_) * HID_ + h * HD_;

    __shared__ float As[8][132];
    __shared__ float Bs[8][128];
    int tid = threadIdx.x;
    int tx = tid & 15, ty = tid >> 4;
    int aRow = tid >> 1;
    int aCol = (tid & 1) * 4;
    int bRow = tid >> 5;
    int bCol = (tid & 31) * 4;
    const float* Ap = A + (size_t)(by * 128 + aRow) * S_ + aCol;
    const float* Bp = Bm + (size_t)bRow * HID_ + bCol;

    int Kend = (by + 1) * 128;  // causal: only k <= q-tile-max contributes
    float acc[8][8] = {};
    for (int k0 = 0; k0 < Kend; k0 += 8) {
        float4 a4 = *(const float4*)(Ap + k0);
        As[aCol + 0][aRow] = a4.x;
        As[aCol + 1][aRow] = a4.y;
        As[aCol + 2][aRow] = a4.z;
        As[aCol + 3][aRow] = a4.w;
        float4 b4 = *(const float4*)(Bp + (size_t)k0 * HID_);
        *(float4*)&Bs[bRow][bCol] = b4;
        __syncthreads();
#pragma unroll
        for (int kk = 0; kk < 8; kk++) {
            float ar[8], br[8];
#pragma unroll
            for (int i = 0; i < 8; i++) ar[i] = As[kk][ty * 8 + i];
#pragma unroll
            for (int j = 0; j < 8; j++) br[j] = Bs[kk][tx * 8 + j];
#pragma unroll
            for (int i = 0; i < 8; i++)
#pragma unroll
                for (int j = 0; j < 8; j++) acc[i][j] += ar[i] * br[j];
        }
        __syncthreads();
    }
#pragma unroll
    for (int i = 0; i < 8; i++) {
        int r = by * 128 + ty * 8 + i;
#pragma unroll
        for (int j = 0; j < 8; j++) {
            C[(size_t)r * HID_ + tx * 8 + j] = acc[i][j];
        }
    }
}

// ---------------- silu(gate) * up ----------------
__global__ void silu_mul(const float* __restrict__ gu, float* __restrict__ act) {
    size_t idx = (size_t)blockIdx.x * 256 + threadIdx.x;
    size_t t = idx / INTER_;
    size_t i = idx - t * INTER_;
    const float* row = gu + t * (2 * INTER_);
    float g = row[i];
    float u = row[INTER_ + i];
    act[idx] = (g / (1.f + expf(-g))) * u;
}

// ---------------- host orchestration ----------------
extern "C" void kernel_launch(void* const* d_in, const int* in_sizes, int n_in,
                              void* d_out, int out_size) {
    const int* input_ids = (const int*)d_in[0];
    const float* cosp = (const float*)d_in[1];
    const float* sinp = (const float*)d_in[2];
    const int* slots = (const int*)d_in[3];
    // d_in[4], d_in[5]: zero-initialized caches (unused; we rebuild in d_out)
    const float* embed = (const float*)d_in[6];
    const float* qkv_w = (const float*)d_in[7];
    const float* qkv_b = (const float*)d_in[8];
    const float* dense_w = (const float*)d_in[9];
    const float* gateup_w = (const float*)d_in[10];
    const float* down_w = (const float*)d_in[11];
    const float* ln1_w = (const float*)d_in[12];
    const float* ln2_w = (const float*)d_in[13];
    const float* final_ln_w = (const float*)d_in[14];

    float* out = (float*)d_out;

    float* scratch = nullptr;
    cudaGetSymbolAddress((void**)&scratch, g_scratch);
    float* h_ = scratch + OFF_H;
    float* res_ = scratch + OFF_RES;
    float* norm_ = scratch + OFF_NORM;
    float* q_ = scratch + OFF_Q;
    float* k_ = scratch + OFF_K;
    float* v_ = scratch + OFF_V;
    float* o_ = scratch + OFF_O;
    float* attn_ = scratch + OFF_ATTN;
    float* qkv_ = scratch + OFF_QKV;
    float* scores_ = scratch + OFF_SCORES;
    float* gu_ = scratch + OFF_GU;
    float* act_ = scratch + OFF_ACT;

    const size_t CACHE = (size_t)NBLK_ * BLK_ * NH_ * HD_;  // per layer
    float* kc_base = out + (size_t)T_ * HID_;
    float* vc_base = kc_base + (size_t)L_ * CACHE;
    bool write_cache =
        (size_t)out_size >= (size_t)T_ * HID_ + 2 * (size_t)L_ * CACHE;
    if (write_cache) {
        cudaMemsetAsync(kc_base, 0, 2 * (size_t)L_ * CACHE * sizeof(float), 0);
    }

    embed_kernel<<<T_, 256>>>(input_ids, embed, h_);

    for (int l = 0; l < L_; l++) {
        const float* qkv_wl = qkv_w + (size_t)l * HID_ * 3 * HID_;
        const float* qkv_bl = qkv_b + (size_t)l * 3 * HID_;
        const float* dense_wl = dense_w + (size_t)l * HID_ * HID_;
        const float* gateup_wl = gateup_w + (size_t)l * HID_ * 2 * INTER_;
        const float* down_wl = down_w + (size_t)l * INTER_ * HID_;

        // pre-attn norm (residual add for l>0)
        rmsnorm_kernel<<<T_, 256>>>(h_, (l == 0) ? nullptr : res_,
                                    ln1_w + (size_t)l * HID_, norm_, res_);

        // qkv projection
        {
            dim3 grid(3 * HID_ / 128, T_ / 128);
            sgemm_nn<<<grid, 256>>>(norm_, qkv_wl, qkv_bl, qkv_, T_, 3 * HID_, HID_);
        }

        // rope + split + cache scatter
        {
            dim3 grid(T_, NH_);
            rope_scatter<<<grid, 128>>>(qkv_, cosp, sinp, slots, q_, k_, v_,
                                        write_cache ? kc_base + (size_t)l * CACHE : nullptr,
                                        write_cache ? vc_base + (size_t)l * CACHE : nullptr);
        }

        // attention
        {
            dim3 grid(S_ / 128, S_ / 128, B_ * NH_);
            scores_kernel<<<grid, 256>>>(q_, k_, scores_);
        }
        softmax_causal<<<B_ * NH_ * S_, 256>>>(scores_);
        {
            dim3 grid(1, S_ / 128, B_ * NH_);
            attn_o_kernel<<<grid, 256>>>(scores_, v_, o_);
        }

        // dense projection
        {
            dim3 grid(HID_ / 128, T_ / 128);
            sgemm_nn<<<grid, 256>>>(o_, dense_wl, nullptr, attn_, T_, HID_, HID_);
        }

        // post-attn norm
        rmsnorm_kernel<<<T_, 256>>>(attn_, res_, ln2_w + (size_t)l * HID_, norm_, res_);

        // MLP
        {
            dim3 grid(2 * INTER_ / 128, T_ / 128);
            sgemm_nn<<<grid, 256>>>(norm_, gateup_wl, nullptr, gu_, T_, 2 * INTER_, HID_);
        }
        silu_mul<<<(T_ * INTER_) / 256, 256>>>(gu_, act_);
        {
            dim3 grid(HID_ / 128, T_ / 128);
            sgemm_nn<<<grid, 256>>>(act_, down_wl, nullptr, h_, T_, HID_, INTER_);
        }
    }

    // final norm -> out
    rmsnorm_kernel<<<T_, 256>>>(h_, res_, final_ln_w, out, nullptr);
}

// round 3
// speedup vs baseline: 1.3487x; 1.3487x over previous
#include <cuda_runtime.h>
#include <math.h>
#include <stdint.h>

// ---------------- model constants ----------------
#define L_     2
#define HID_   4096
#define NH_    32
#define HD_    128
#define INTER_ 13696
#define B_     2
#define S_     1024
#define T_     2048
#define NBLK_  160
#define BLK_   16
#define ROT_   64
#define NFREQ_ 32
#define EPS_   1e-5f
#define SCALE_ 0.08838834764831845f   // HD^-0.5

// ---------------- scratch (device globals; no allocation) ----------------
#define OFF_H      ((size_t)0)
#define OFF_RES    ((size_t)8388608)
#define OFF_NORM   ((size_t)16777216)
#define OFF_Q      ((size_t)25165824)
#define OFF_K      ((size_t)33554432)
#define OFF_V      ((size_t)41943040)
#define OFF_O      ((size_t)50331648)
#define OFF_ATTN   ((size_t)58720256)
#define OFF_QKV    ((size_t)67108864)   // 25165824 floats
#define OFF_SCORES ((size_t)92274688)   // 67108864 floats
#define OFF_GU     ((size_t)159383552)  // 56098816 floats
#define OFF_ACT    ((size_t)215482368)  // 28049408 floats
#define SCRATCH_TOTAL ((size_t)243531776)

__device__ float g_scratch[SCRATCH_TOTAL];

__device__ __forceinline__ void split_tf32(float x, uint32_t& hi, uint32_t& lo) {
    uint32_t h;
    asm("cvt.rna.tf32.f32 %0, %1;" : "=r"(h) : "f"(x));
    float lf = x - __uint_as_float(h);
    uint32_t l;
    asm("cvt.rna.tf32.f32 %0, %1;" : "=r"(l) : "f"(lf));
    hi = h;
    lo = l;
}

// ---------------- embedding gather ----------------
__global__ void embed_kernel(const int* __restrict__ ids,
                             const float* __restrict__ E,
                             float* __restrict__ h) {
    int t = blockIdx.x;
    int id = ids[t];
    const float* er = E + (size_t)id * HID_;
    float* hr = h + (size_t)t * HID_;
    for (int i = threadIdx.x; i < HID_; i += 256) hr[i] = er[i];
}

// ---------------- fused (residual-add) RMSNorm ----------------
__global__ void rmsnorm_kernel(const float* __restrict__ x,
                               const float* __restrict__ resin,
                               const float* __restrict__ w,
                               float* __restrict__ outn,
                               float* __restrict__ resout) {
    int t = blockIdx.x, tid = threadIdx.x;
    const float* xr = x + (size_t)t * HID_;
    const float* rr = resin ? resin + (size_t)t * HID_ : nullptr;
    float* on = outn + (size_t)t * HID_;
    float* ro = resout ? resout + (size_t)t * HID_ : nullptr;

    float v[16];
    float ss = 0.f;
#pragma unroll
    for (int i = 0; i < 16; i++) {
        int c = tid + i * 256;
        float a = xr[c];
        if (rr) a += rr[c];
        v[i] = a;
        ss += a * a;
    }
    __shared__ float red[8];
#pragma unroll
    for (int o = 16; o; o >>= 1) ss += __shfl_xor_sync(0xffffffffu, ss, o);
    if ((tid & 31) == 0) red[tid >> 5] = ss;
    __syncthreads();
    float tot = 0.f;
#pragma unroll
    for (int i = 0; i < 8; i++) tot += red[i];
    float inv = rsqrtf(tot * (1.0f / HID_) + EPS_);
#pragma unroll
    for (int i = 0; i < 16; i++) {
        int c = tid + i * 256;
        if (ro) ro[c] = v[i];
        on[c] = w[c] * v[i] * inv;
    }
}

// ============================================================
// TF32x3 tensor-core GEMM (error-compensated; ~fp32 accuracy).
// 128x128 CTA tile, k-tile 16, 8 warps, warp tile 64x32 via
// 4x4 m16n8k8 mma.sync; each operand split hi/lo in registers,
// 3 mma passes: a_hi*b_lo + a_lo*b_hi + a_hi*b_hi.
//
// MODE 0: C = A(row, lda) @ B(row, ldb) [+bias], plain NN.
// MODE 1: scores — per (b,h): C = scale * Q @ K^T, causal tile skip.
// MODE 2: PV — per (b,h): O = P @ V with causal K-limit = (by+1)*128.
// ============================================================
template<int MODE>
__global__ void __launch_bounds__(256) gemm_tf32(
    const float* __restrict__ Ag, const float* __restrict__ Bg,
    const float* __restrict__ bias, float* __restrict__ Cg,
    int K, int lda, int ldb, int ldc)
{
    int bx = blockIdx.x, by = blockIdx.y, bz = blockIdx.z;
    const float* A = Ag;
    const float* B = Bg;
    float* C = Cg;
    if (MODE == 1) {
        if (bx > by) return;          // fully masked causal tile
        int b = bz >> 5, h = bz & 31;
        A += ((size_t)b * S_) * lda + h * HD_;
        B += ((size_t)b * S_) * ldb + h * HD_;
        C += (size_t)bz * S_ * S_;
        K = HD_;
    } else if (MODE == 2) {
        int b = bz >> 5, h = bz & 31;
        A += (size_t)bz * S_ * S_;
        B += ((size_t)b * S_) * ldb + h * HD_;
        C += ((size_t)b * S_) * ldc + h * HD_;
        K = (by + 1) * 128;           // causal K-limit
    }

    __shared__ float As[2][16][136];
    __shared__ float Bs[2][16][136];

    int tid = threadIdx.x;
    int lane = tid & 31, warp = tid >> 5;
    int g = lane >> 2, tg = lane & 3;
    int wm = (warp & 1) * 64;
    int wn = (warp >> 1) * 32;

    // ---- fill indexing ----
    int ar = tid >> 1;            // 0..127 (tile row)
    int ak = (tid & 1) * 8;       // 0 or 8
    const float* Aptr = A + (size_t)(by * 128 + ar) * lda + ak;

    const float* Bptr;
    int bk = 0, bn = 0;
    if (MODE == 1) {
        Bptr = B + (size_t)(bx * 128 + ar) * ldb + ak;   // same pattern as A
    } else {
        bk = tid >> 4;            // 0..15
        bn = (tid & 15) * 8;      // 0..120
        Bptr = B + (size_t)bk * ldb + bx * 128 + bn;
    }

    float4 pa0, pa1, pb0, pb1;

    auto ldg_tile = [&](int k0) {
        pa0 = *(const float4*)(Aptr + k0);
        pa1 = *(const float4*)(Aptr + k0 + 4);
        if (MODE == 1) {
            pb0 = *(const float4*)(Bptr + k0);
            pb1 = *(const float4*)(Bptr + k0 + 4);
        } else {
            pb0 = *(const float4*)(Bptr + (size_t)k0 * ldb);
            pb1 = *(const float4*)(Bptr + (size_t)k0 * ldb + 4);
        }
    };

    auto sts_tile = [&](int buf) {
        As[buf][ak + 0][ar] = pa0.x;
        As[buf][ak + 1][ar] = pa0.y;
        As[buf][ak + 2][ar] = pa0.z;
        As[buf][ak + 3][ar] = pa0.w;
        As[buf][ak + 4][ar] = pa1.x;
        As[buf][ak + 5][ar] = pa1.y;
        As[buf][ak + 6][ar] = pa1.z;
        As[buf][ak + 7][ar] = pa1.w;
        if (MODE == 1) {
            Bs[buf][ak + 0][ar] = pb0.x;
            Bs[buf][ak + 1][ar] = pb0.y;
            Bs[buf][ak + 2][ar] = pb0.z;
            Bs[buf][ak + 3][ar] = pb0.w;
            Bs[buf][ak + 4][ar] = pb1.x;
            Bs[buf][ak + 5][ar] = pb1.y;
            Bs[buf][ak + 6][ar] = pb1.z;
            Bs[buf][ak + 7][ar] = pb1.w;
        } else {
            *(float4*)&Bs[buf][bk][bn + 0] = pb0;
            *(float4*)&Bs[buf][bk][bn + 4] = pb1;
        }
    };

    float acc[4][4][4] = {};

#define MMA_TF32(ACC, A0, A1, A2, A3, B0, B1)                                  \
    asm volatile(                                                              \
        "mma.sync.aligned.m16n8k8.row.col.f32.tf32.tf32.f32 "                  \
        "{%0,%1,%2,%3}, {%4,%5,%6,%7}, {%8,%9}, {%0,%1,%2,%3};"                \
        : "+f"((ACC)[0]), "+f"((ACC)[1]), "+f"((ACC)[2]), "+f"((ACC)[3])       \
        : "r"(A0), "r"(A1), "r"(A2), "r"(A3), "r"(B0), "r"(B1))

    auto compute = [&](int buf) {
        uint32_t ah[4][4], al[4][4], bh[4][2], bl[4][2];
#pragma unroll
        for (int ks = 0; ks < 2; ks++) {
            int k0 = ks * 8;
#pragma unroll
            for (int mt = 0; mt < 4; mt++) {
                int m = wm + mt * 16 + g;
                split_tf32(As[buf][k0 + tg][m],     ah[mt][0], al[mt][0]);
                split_tf32(As[buf][k0 + tg][m + 8], ah[mt][1], al[mt][1]);
                split_tf32(As[buf][k0 + tg + 4][m],     ah[mt][2], al[mt][2]);
                split_tf32(As[buf][k0 + tg + 4][m + 8], ah[mt][3], al[mt][3]);
            }
#pragma unroll
            for (int nt = 0; nt < 4; nt++) {
                int n = wn + nt * 8 + g;
                split_tf32(Bs[buf][k0 + tg][n],     bh[nt][0], bl[nt][0]);
                split_tf32(Bs[buf][k0 + tg + 4][n], bh[nt][1], bl[nt][1]);
            }
#pragma unroll
            for (int mt = 0; mt < 4; mt++)
#pragma unroll
                for (int nt = 0; nt < 4; nt++) {
                    MMA_TF32(acc[mt][nt], ah[mt][0], ah[mt][1], ah[mt][2],
                             ah[mt][3], bl[nt][0], bl[nt][1]);
                    MMA_TF32(acc[mt][nt], al[mt][0], al[mt][1], al[mt][2],
                             al[mt][3], bh[nt][0], bh[nt][1]);
                    MMA_TF32(acc[mt][nt], ah[mt][0], ah[mt][1], ah[mt][2],
                             ah[mt][3], bh[nt][0], bh[nt][1]);
                }
        }
    };

    int nk = K / 16;
    ldg_tile(0);
    sts_tile(0);
    __syncthreads();
    for (int kt = 0; kt < nk; kt++) {
        int buf = kt & 1;
        if (kt + 1 < nk) ldg_tile((kt + 1) * 16);
        compute(buf);
        if (kt + 1 < nk) sts_tile(buf ^ 1);
        __syncthreads();
    }

    // ---- epilogue ----
#pragma unroll
    for (int mt = 0; mt < 4; mt++) {
#pragma unroll
        for (int i = 0; i < 2; i++) {
            int r = by * 128 + wm + mt * 16 + g + i * 8;
#pragma unroll
            for (int nt = 0; nt < 4; nt++) {
                int c = bx * 128 + wn + nt * 8 + 2 * tg;
                float v0 = acc[mt][nt][i * 2 + 0];
                float v1 = acc[mt][nt][i * 2 + 1];
                if (MODE == 0 && bias) {
                    v0 += bias[c];
                    v1 += bias[c + 1];
                }
                if (MODE == 1) {
                    v0 *= SCALE_;
                    v1 *= SCALE_;
                }
                *(float2*)&C[(size_t)r * ldc + c] = make_float2(v0, v1);
            }
        }
    }
}

// ---------------- rope + split + KV-cache scatter ----------------
__global__ void rope_scatter(const float* __restrict__ qkv,
                             const float* __restrict__ cosp,
                             const float* __restrict__ sinp,
                             const int* __restrict__ slots,
                             float* __restrict__ q, float* __restrict__ k,
                             float* __restrict__ v,
                             float* __restrict__ kc, float* __restrict__ vc) {
    int t = blockIdx.x, h = blockIdx.y, d = threadIdx.x;
    const float* row = qkv + (size_t)t * (3 * HID_);
    float qv, kv;
    if (d < ROT_) {
        int f = d >> 1;
        float c = cosp[t * NFREQ_ + f];
        float s = sinp[t * NFREQ_ + f];
        float q0 = row[h * HD_ + f * 2];
        float q1 = row[h * HD_ + f * 2 + 1];
        float k0 = row[HID_ + h * HD_ + f * 2];
        float k1 = row[HID_ + h * HD_ + f * 2 + 1];
        if (d & 1) {
            qv = q1 * c + q0 * s;
            kv = k1 * c + k0 * s;
        } else {
            qv = q0 * c - q1 * s;
            kv = k0 * c - k1 * s;
        }
    } else {
        qv = row[h * HD_ + d];
        kv = row[HID_ + h * HD_ + d];
    }
    float vv = row[2 * HID_ + h * HD_ + d];
    size_t o = (size_t)t * HID_ + h * HD_ + d;
    q[o] = qv;
    k[o] = kv;
    v[o] = vv;
    if (kc) {
        int slot = slots[t];
        size_t co = ((size_t)slot * NH_ + h) * HD_ + d;
        kc[co] = kv;
        vc[co] = vv;
    }
}

// ---------------- causal softmax (in place, zero-fills above diagonal) ----
__global__ void softmax_causal(float* __restrict__ Sc) {
    int row = blockIdx.x;               // (b*NH + h)*S + qi
    int qi = row & (S_ - 1);
    float* sr = Sc + (size_t)row * S_;
    int n = qi + 1;
    int tid = threadIdx.x;
    __shared__ float red[8];

    float m = -1e30f;
    for (int k = tid; k < n; k += 256) m = fmaxf(m, sr[k]);
#pragma unroll
    for (int o = 16; o; o >>= 1) m = fmaxf(m, __shfl_xor_sync(0xffffffffu, m, o));
    if ((tid & 31) == 0) red[tid >> 5] = m;
    __syncthreads();
    float mm = red[0];
#pragma unroll
    for (int i = 1; i < 8; i++) mm = fmaxf(mm, red[i]);
    __syncthreads();

    float sum = 0.f;
    for (int k = tid; k < n; k += 256) {
        float e = expf(sr[k] - mm);
        sr[k] = e;
        sum += e;
    }
#pragma unroll
    for (int o = 16; o; o >>= 1) sum += __shfl_xor_sync(0xffffffffu, sum, o);
    if ((tid & 31) == 0) red[tid >> 5] = sum;
    __syncthreads();
    float tot = 0.f;
#pragma unroll
    for (int i = 0; i < 8; i++) tot += red[i];
    float inv = 1.f / tot;
    for (int k = tid; k < n; k += 256) sr[k] *= inv;
    for (int k = n + tid; k < S_; k += 256) sr[k] = 0.f;  // needed by PV tiles
}

// ---------------- silu(gate) * up ----------------
__global__ void silu_mul(const float* __restrict__ gu, float* __restrict__ act) {
    size_t idx = (size_t)blockIdx.x * 256 + threadIdx.x;
    size_t t = idx / INTER_;
    size_t i = idx - t * INTER_;
    const float* row = gu + t * (2 * INTER_);
    float g = row[i];
    float u = row[INTER_ + i];
    act[idx] = (g / (1.f + expf(-g))) * u;
}

// ---------------- host orchestration ----------------
extern "C" void kernel_launch(void* const* d_in, const int* in_sizes, int n_in,
                              void* d_out, int out_size) {
    const int* input_ids = (const int*)d_in[0];
    const float* cosp = (const float*)d_in[1];
    const float* sinp = (const float*)d_in[2];
    const int* slots = (const int*)d_in[3];
    const float* embed = (const float*)d_in[6];
    const float* qkv_w = (const float*)d_in[7];
    const float* qkv_b = (const float*)d_in[8];
    const float* dense_w = (const float*)d_in[9];
    const float* gateup_w = (const float*)d_in[10];
    const float* down_w = (const float*)d_in[11];
    const float* ln1_w = (const float*)d_in[12];
    const float* ln2_w = (const float*)d_in[13];
    const float* final_ln_w = (const float*)d_in[14];

    float* out = (float*)d_out;

    float* scratch = nullptr;
    cudaGetSymbolAddress((void**)&scratch, g_scratch);
    float* h_ = scratch + OFF_H;
    float* res_ = scratch + OFF_RES;
    float* norm_ = scratch + OFF_NORM;
    float* q_ = scratch + OFF_Q;
    float* k_ = scratch + OFF_K;
    float* v_ = scratch + OFF_V;
    float* o_ = scratch + OFF_O;
    float* attn_ = scratch + OFF_ATTN;
    float* qkv_ = scratch + OFF_QKV;
    float* scores_ = scratch + OFF_SCORES;
    float* gu_ = scratch + OFF_GU;
    float* act_ = scratch + OFF_ACT;

    const size_t CACHE = (size_t)NBLK_ * BLK_ * NH_ * HD_;  // per layer
    float* kc_base = out + (size_t)T_ * HID_;
    float* vc_base = kc_base + (size_t)L_ * CACHE;
    bool write_cache =
        (size_t)out_size >= (size_t)T_ * HID_ + 2 * (size_t)L_ * CACHE;
    if (write_cache) {
        cudaMemsetAsync(kc_base, 0, 2 * (size_t)L_ * CACHE * sizeof(float), 0);
    }

    embed_kernel<<<T_, 256>>>(input_ids, embed, h_);

    for (int l = 0; l < L_; l++) {
        const float* qkv_wl = qkv_w + (size_t)l * HID_ * 3 * HID_;
        const float* qkv_bl = qkv_b + (size_t)l * 3 * HID_;
        const float* dense_wl = dense_w + (size_t)l * HID_ * HID_;
        const float* gateup_wl = gateup_w + (size_t)l * HID_ * 2 * INTER_;
        const float* down_wl = down_w + (size_t)l * INTER_ * HID_;

        // pre-attn norm (residual add for l>0)
        rmsnorm_kernel<<<T_, 256>>>(h_, (l == 0) ? nullptr : res_,
                                    ln1_w + (size_t)l * HID_, norm_, res_);

        // qkv projection
        gemm_tf32<0><<<dim3(3 * HID_ / 128, T_ / 128), 256>>>(
            norm_, qkv_wl, qkv_bl, qkv_, HID_, HID_, 3 * HID_, 3 * HID_);

        // rope + split + cache scatter
        {
            dim3 grid(T_, NH_);
            rope_scatter<<<grid, 128>>>(qkv_, cosp, sinp, slots, q_, k_, v_,
                                        write_cache ? kc_base + (size_t)l * CACHE : nullptr,
                                        write_cache ? vc_base + (size_t)l * CACHE : nullptr);
        }

        // attention: scores = scale * Q @ K^T (causal tile skip)
        gemm_tf32<1><<<dim3(S_ / 128, S_ / 128, B_ * NH_), 256>>>(
            q_, k_, nullptr, scores_, HD_, HID_, HID_, S_);

        softmax_causal<<<B_ * NH_ * S_, 256>>>(scores_);

        // O = P @ V (causal K-limit)
        gemm_tf32<2><<<dim3(1, S_ / 128, B_ * NH_), 256>>>(
            scores_, v_, nullptr, o_, 0, S_, HID_, HID_);

        // dense projection
        gemm_tf32<0><<<dim3(HID_ / 128, T_ / 128), 256>>>(
            o_, dense_wl, nullptr, attn_, HID_, HID_, HID_, HID_);

        // post-attn norm
        rmsnorm_kernel<<<T_, 256>>>(attn_, res_, ln2_w + (size_t)l * HID_, norm_, res_);

        // MLP
        gemm_tf32<0><<<dim3(2 * INTER_ / 128, T_ / 128), 256>>>(
            norm_, gateup_wl, nullptr, gu_, HID_, HID_, 2 * INTER_, 2 * INTER_);

        silu_mul<<<(T_ * INTER_) / 256, 256>>>(gu_, act_);

        gemm_tf32<0><<<dim3(HID_ / 128, T_ / 128), 256>>>(
            act_, down_wl, nullptr, h_, INTER_, INTER_, HID_, HID_);
    }

    // final norm -> out
    rmsnorm_kernel<<<T_, 256>>>(h_, res_, final_ln_w, out, nullptr);
}

// round 4
// speedup vs baseline: 1.3506x; 1.0014x over previous
#include <cuda_runtime.h>
#include <math.h>
#include <stdint.h>

// ---------------- model constants ----------------
#define L_     2
#define HID_   4096
#define NH_    32
#define HD_    128
#define INTER_ 13696
#define B_     2
#define S_     1024
#define T_     2048
#define NBLK_  160
#define BLK_   16
#define ROT_   64
#define NFREQ_ 32
#define EPS_   1e-5f
#define SCALE_ 0.08838834764831845f   // HD^-0.5

// ---------------- scratch (device globals; no allocation) ----------------
#define OFF_H      ((size_t)0)
#define OFF_RES    ((size_t)8388608)
#define OFF_NORM   ((size_t)16777216)
#define OFF_Q      ((size_t)25165824)
#define OFF_K      ((size_t)33554432)
#define OFF_V      ((size_t)41943040)
#define OFF_O      ((size_t)50331648)
#define OFF_ATTN   ((size_t)58720256)
#define OFF_QKV    ((size_t)67108864)   // 25165824 floats
#define OFF_SCORES ((size_t)92274688)   // 67108864 floats
#define OFF_GU     ((size_t)159383552)  // 56098816 floats
#define OFF_ACT    ((size_t)215482368)  // 28049408 floats
#define SCRATCH_TOTAL ((size_t)243531776)

__device__ float g_scratch[SCRATCH_TOTAL];

__device__ __forceinline__ void split_tf32(float x, uint32_t& hi, uint32_t& lo) {
    uint32_t h;
    asm("cvt.rna.tf32.f32 %0, %1;" : "=r"(h) : "f"(x));
    float lf = x - __uint_as_float(h);
    uint32_t l;
    asm("cvt.rna.tf32.f32 %0, %1;" : "=r"(l) : "f"(lf));
    hi = h;
    lo = l;
}

// ---------------- embedding gather ----------------
__global__ void embed_kernel(const int* __restrict__ ids,
                             const float* __restrict__ E,
                             float* __restrict__ h) {
    int t = blockIdx.x;
    int id = ids[t];
    const float* er = E + (size_t)id * HID_;
    float* hr = h + (size_t)t * HID_;
    for (int i = threadIdx.x; i < HID_; i += 256) hr[i] = er[i];
}

// ---------------- fused (residual-add) RMSNorm ----------------
__global__ void rmsnorm_kernel(const float* __restrict__ x,
                               const float* __restrict__ resin,
                               const float* __restrict__ w,
                               float* __restrict__ outn,
                               float* __restrict__ resout) {
    int t = blockIdx.x, tid = threadIdx.x;
    const float* xr = x + (size_t)t * HID_;
    const float* rr = resin ? resin + (size_t)t * HID_ : nullptr;
    float* on = outn + (size_t)t * HID_;
    float* ro = resout ? resout + (size_t)t * HID_ : nullptr;

    float v[16];
    float ss = 0.f;
#pragma unroll
    for (int i = 0; i < 16; i++) {
        int c = tid + i * 256;
        float a = xr[c];
        if (rr) a += rr[c];
        v[i] = a;
        ss += a * a;
    }
    __shared__ float red[8];
#pragma unroll
    for (int o = 16; o; o >>= 1) ss += __shfl_xor_sync(0xffffffffu, ss, o);
    if ((tid & 31) == 0) red[tid >> 5] = ss;
    __syncthreads();
    float tot = 0.f;
#pragma unroll
    for (int i = 0; i < 8; i++) tot += red[i];
    float inv = rsqrtf(tot * (1.0f / HID_) + EPS_);
#pragma unroll
    for (int i = 0; i < 16; i++) {
        int c = tid + i * 256;
        if (ro) ro[c] = v[i];
        on[c] = w[c] * v[i] * inv;
    }
}

// ============================================================
// TF32x3 tensor-core GEMM (error-compensated; ~fp32 accuracy).
// 128x128 CTA tile, k-tile 16, 8 warps, warp tile 64x32 via
// 4x4 m16n8k8 mma.sync; each operand split hi/lo in registers,
// 3 mma passes: a_hi*b_lo + a_lo*b_hi + a_hi*b_hi.
//
// MODE 0: C = A(row, lda) @ B(row, ldb) [+bias], plain NN.
// MODE 1: scores — per (b,h): C = scale * Q @ K^T, causal tile skip.
// MODE 2: PV — per (b,h): O = P @ V with causal K-limit = (by+1)*128.
// ============================================================
template<int MODE>
__global__ void __launch_bounds__(256) gemm_tf32(
    const float* __restrict__ Ag, const float* __restrict__ Bg,
    const float* __restrict__ bias, float* __restrict__ Cg,
    int K, int lda, int ldb, int ldc)
{
    int bx = blockIdx.x, by = blockIdx.y, bz = blockIdx.z;
    const float* A = Ag;
    const float* B = Bg;
    float* C = Cg;
    if (MODE == 1) {
        if (bx > by) return;          // fully masked causal tile
        int b = bz >> 5, h = bz & 31;
        A += ((size_t)b * S_) * lda + h * HD_;
        B += ((size_t)b * S_) * ldb + h * HD_;
        C += (size_t)bz * S_ * S_;
        K = HD_;
    } else if (MODE == 2) {
        int b = bz >> 5, h = bz & 31;
        A += (size_t)bz * S_ * S_;
        B += ((size_t)b * S_) * ldb + h * HD_;
        C += ((size_t)b * S_) * ldc + h * HD_;
        K = (by + 1) * 128;           // causal K-limit
    }

    __shared__ float As[2][16][136];
    __shared__ float Bs[2][16][136];

    int tid = threadIdx.x;
    int lane = tid & 31, warp = tid >> 5;
    int g = lane >> 2, tg = lane & 3;
    int wm = (warp & 1) * 64;
    int wn = (warp >> 1) * 32;

    // ---- fill indexing ----
    int ar = tid >> 1;            // 0..127 (tile row)
    int ak = (tid & 1) * 8;       // 0 or 8
    const float* Aptr = A + (size_t)(by * 128 + ar) * lda + ak;

    const float* Bptr;
    int bk = 0, bn = 0;
    if (MODE == 1) {
        Bptr = B + (size_t)(bx * 128 + ar) * ldb + ak;   // same pattern as A
    } else {
        bk = tid >> 4;            // 0..15
        bn = (tid & 15) * 8;      // 0..120
        Bptr = B + (size_t)bk * ldb + bx * 128 + bn;
    }

    float4 pa0, pa1, pb0, pb1;

    auto ldg_tile = [&](int k0) {
        pa0 = *(const float4*)(Aptr + k0);
        pa1 = *(const float4*)(Aptr + k0 + 4);
        if (MODE == 1) {
            pb0 = *(const float4*)(Bptr + k0);
            pb1 = *(const float4*)(Bptr + k0 + 4);
        } else {
            pb0 = *(const float4*)(Bptr + (size_t)k0 * ldb);
            pb1 = *(const float4*)(Bptr + (size_t)k0 * ldb + 4);
        }
    };

    auto sts_tile = [&](int buf) {
        As[buf][ak + 0][ar] = pa0.x;
        As[buf][ak + 1][ar] = pa0.y;
        As[buf][ak + 2][ar] = pa0.z;
        As[buf][ak + 3][ar] = pa0.w;
        As[buf][ak + 4][ar] = pa1.x;
        As[buf][ak + 5][ar] = pa1.y;
        As[buf][ak + 6][ar] = pa1.z;
        As[buf][ak + 7][ar] = pa1.w;
        if (MODE == 1) {
            Bs[buf][ak + 0][ar] = pb0.x;
            Bs[buf][ak + 1][ar] = pb0.y;
            Bs[buf][ak + 2][ar] = pb0.z;
            Bs[buf][ak + 3][ar] = pb0.w;
            Bs[buf][ak + 4][ar] = pb1.x;
            Bs[buf][ak + 5][ar] = pb1.y;
            Bs[buf][ak + 6][ar] = pb1.z;
            Bs[buf][ak + 7][ar] = pb1.w;
        } else {
            *(float4*)&Bs[buf][bk][bn + 0] = pb0;
            *(float4*)&Bs[buf][bk][bn + 4] = pb1;
        }
    };

    float acc[4][4][4] = {};

#define MMA_TF32(ACC, A0, A1, A2, A3, B0, B1)                                  \
    asm volatile(                                                              \
        "mma.sync.aligned.m16n8k8.row.col.f32.tf32.tf32.f32 "                  \
        "{%0,%1,%2,%3}, {%4,%5,%6,%7}, {%8,%9}, {%0,%1,%2,%3};"                \
        : "+f"((ACC)[0]), "+f"((ACC)[1]), "+f"((ACC)[2]), "+f"((ACC)[3])       \
        : "r"(A0), "r"(A1), "r"(A2), "r"(A3), "r"(B0), "r"(B1))

    auto compute = [&](int buf) {
        uint32_t ah[4][4], al[4][4], bh[4][2], bl[4][2];
#pragma unroll
        for (int ks = 0; ks < 2; ks++) {
            int k0 = ks * 8;
#pragma unroll
            for (int mt = 0; mt < 4; mt++) {
                int m = wm + mt * 16 + g;
                split_tf32(As[buf][k0 + tg][m],     ah[mt][0], al[mt][0]);
                split_tf32(As[buf][k0 + tg][m + 8], ah[mt][1], al[mt][1]);
                split_tf32(As[buf][k0 + tg + 4][m],     ah[mt][2], al[mt][2]);
                split_tf32(As[buf][k0 + tg + 4][m + 8], ah[mt][3], al[mt][3]);
            }
#pragma unroll
            for (int nt = 0; nt < 4; nt++) {
                int n = wn + nt * 8 + g;
                split_tf32(Bs[buf][k0 + tg][n],     bh[nt][0], bl[nt][0]);
                split_tf32(Bs[buf][k0 + tg + 4][n], bh[nt][1], bl[nt][1]);
            }
#pragma unroll
            for (int mt = 0; mt < 4; mt++)
#pragma unroll
                for (int nt = 0; nt < 4; nt++) {
                    MMA_TF32(acc[mt][nt], ah[mt][0], ah[mt][1], ah[mt][2],
                             ah[mt][3], bl[nt][0], bl[nt][1]);
                    MMA_TF32(acc[mt][nt], al[mt][0], al[mt][1], al[mt][2],
                             al[mt][3], bh[nt][0], bh[nt][1]);
                    MMA_TF32(acc[mt][nt], ah[mt][0], ah[mt][1], ah[mt][2],
                             ah[mt][3], bh[nt][0], bh[nt][1]);
                }
        }
    };

    int nk = K / 16;
    ldg_tile(0);
    sts_tile(0);
    __syncthreads();
    for (int kt = 0; kt < nk; kt++) {
        int buf = kt & 1;
        if (kt + 1 < nk) ldg_tile((kt + 1) * 16);
        compute(buf);
        if (kt + 1 < nk) sts_tile(buf ^ 1);
        __syncthreads();
    }

    // ---- epilogue ----
#pragma unroll
    for (int mt = 0; mt < 4; mt++) {
#pragma unroll
        for (int i = 0; i < 2; i++) {
            int r = by * 128 + wm + mt * 16 + g + i * 8;
#pragma unroll
            for (int nt = 0; nt < 4; nt++) {
                int c = bx * 128 + wn + nt * 8 + 2 * tg;
                float v0 = acc[mt][nt][i * 2 + 0];
                float v1 = acc[mt][nt][i * 2 + 1];
                if (MODE == 0 && bias) {
                    v0 += bias[c];
                    v1 += bias[c + 1];
                }
                if (MODE == 1) {
                    v0 *= SCALE_;
                    v1 *= SCALE_;
                }
                *(float2*)&C[(size_t)r * ldc + c] = make_float2(v0, v1);
            }
        }
    }
}

// ---------------- rope + split + KV-cache scatter ----------------
__global__ void rope_scatter(const float* __restrict__ qkv,
                             const float* __restrict__ cosp,
                             const float* __restrict__ sinp,
                             const int* __restrict__ slots,
                             float* __restrict__ q, float* __restrict__ k,
                             float* __restrict__ v,
                             float* __restrict__ kc, float* __restrict__ vc) {
    int t = blockIdx.x, h = blockIdx.y, d = threadIdx.x;
    const float* row = qkv + (size_t)t * (3 * HID_);
    float qv, kv;
    if (d < ROT_) {
        int f = d >> 1;
        float c = cosp[t * NFREQ_ + f];
        float s = sinp[t * NFREQ_ + f];
        float q0 = row[h * HD_ + f * 2];
        float q1 = row[h * HD_ + f * 2 + 1];
        float k0 = row[HID_ + h * HD_ + f * 2];
        float k1 = row[HID_ + h * HD_ + f * 2 + 1];
        if (d & 1) {
            qv = q1 * c + q0 * s;
            kv = k1 * c + k0 * s;
        } else {
            qv = q0 * c - q1 * s;
            kv = k0 * c - k1 * s;
        }
    } else {
        qv = row[h * HD_ + d];
        kv = row[HID_ + h * HD_ + d];
    }
    float vv = row[2 * HID_ + h * HD_ + d];
    size_t o = (size_t)t * HID_ + h * HD_ + d;
    q[o] = qv;
    k[o] = kv;
    v[o] = vv;
    if (kc) {
        int slot = slots[t];
        size_t co = ((size_t)slot * NH_ + h) * HD_ + d;
        kc[co] = kv;
        vc[co] = vv;
    }
}

// ---------------- causal softmax (in place, zero-fills above diagonal) ----
__global__ void softmax_causal(float* __restrict__ Sc) {
    int row = blockIdx.x;               // (b*NH + h)*S + qi
    int qi = row & (S_ - 1);
    float* sr = Sc + (size_t)row * S_;
    int n = qi + 1;
    int tid = threadIdx.x;
    __shared__ float red[8];

    float m = -1e30f;
    for (int k = tid; k < n; k += 256) m = fmaxf(m, sr[k]);
#pragma unroll
    for (int o = 16; o; o >>= 1) m = fmaxf(m, __shfl_xor_sync(0xffffffffu, m, o));
    if ((tid & 31) == 0) red[tid >> 5] = m;
    __syncthreads();
    float mm = red[0];
#pragma unroll
    for (int i = 1; i < 8; i++) mm = fmaxf(mm, red[i]);
    __syncthreads();

    float sum = 0.f;
    for (int k = tid; k < n; k += 256) {
        float e = expf(sr[k] - mm);
        sr[k] = e;
        sum += e;
    }
#pragma unroll
    for (int o = 16; o; o >>= 1) sum += __shfl_xor_sync(0xffffffffu, sum, o);
    if ((tid & 31) == 0) red[tid >> 5] = sum;
    __syncthreads();
    float tot = 0.f;
#pragma unroll
    for (int i = 0; i < 8; i++) tot += red[i];
    float inv = 1.f / tot;
    for (int k = tid; k < n; k += 256) sr[k] *= inv;
    for (int k = n + tid; k < S_; k += 256) sr[k] = 0.f;  // needed by PV tiles
}

// ---------------- silu(gate) * up ----------------
__global__ void silu_mul(const float* __restrict__ gu, float* __restrict__ act) {
    size_t idx = (size_t)blockIdx.x * 256 + threadIdx.x;
    size_t t = idx / INTER_;
    size_t i = idx - t * INTER_;
    const float* row = gu + t * (2 * INTER_);
    float g = row[i];
    float u = row[INTER_ + i];
    act[idx] = (g / (1.f + expf(-g))) * u;
}

// ---------------- host orchestration ----------------
extern "C" void kernel_launch(void* const* d_in, const int* in_sizes, int n_in,
                              void* d_out, int out_size) {
    const int* input_ids = (const int*)d_in[0];
    const float* cosp = (const float*)d_in[1];
    const float* sinp = (const float*)d_in[2];
    const int* slots = (const int*)d_in[3];
    const float* embed = (const float*)d_in[6];
    const float* qkv_w = (const float*)d_in[7];
    const float* qkv_b = (const float*)d_in[8];
    const float* dense_w = (const float*)d_in[9];
    const float* gateup_w = (const float*)d_in[10];
    const float* down_w = (const float*)d_in[11];
    const float* ln1_w = (const float*)d_in[12];
    const float* ln2_w = (const float*)d_in[13];
    const float* final_ln_w = (const float*)d_in[14];

    float* out = (float*)d_out;

    float* scratch = nullptr;
    cudaGetSymbolAddress((void**)&scratch, g_scratch);
    float* h_ = scratch + OFF_H;
    float* res_ = scratch + OFF_RES;
    float* norm_ = scratch + OFF_NORM;
    float* q_ = scratch + OFF_Q;
    float* k_ = scratch + OFF_K;
    float* v_ = scratch + OFF_V;
    float* o_ = scratch + OFF_O;
    float* attn_ = scratch + OFF_ATTN;
    float* qkv_ = scratch + OFF_QKV;
    float* scores_ = scratch + OFF_SCORES;
    float* gu_ = scratch + OFF_GU;
    float* act_ = scratch + OFF_ACT;

    const size_t CACHE = (size_t)NBLK_ * BLK_ * NH_ * HD_;  // per layer
    float* kc_base = out + (size_t)T_ * HID_;
    float* vc_base = kc_base + (size_t)L_ * CACHE;
    bool write_cache =
        (size_t)out_size >= (size_t)T_ * HID_ + 2 * (size_t)L_ * CACHE;
    if (write_cache) {
        cudaMemsetAsync(kc_base, 0, 2 * (size_t)L_ * CACHE * sizeof(float), 0);
    }

    embed_kernel<<<T_, 256>>>(input_ids, embed, h_);

    for (int l = 0; l < L_; l++) {
        const float* qkv_wl = qkv_w + (size_t)l * HID_ * 3 * HID_;
        const float* qkv_bl = qkv_b + (size_t)l * 3 * HID_;
        const float* dense_wl = dense_w + (size_t)l * HID_ * HID_;
        const float* gateup_wl = gateup_w + (size_t)l * HID_ * 2 * INTER_;
        const float* down_wl = down_w + (size_t)l * INTER_ * HID_;

        // pre-attn norm (residual add for l>0)
        rmsnorm_kernel<<<T_, 256>>>(h_, (l == 0) ? nullptr : res_,
                                    ln1_w + (size_t)l * HID_, norm_, res_);

        // qkv projection
        gemm_tf32<0><<<dim3(3 * HID_ / 128, T_ / 128), 256>>>(
            norm_, qkv_wl, qkv_bl, qkv_, HID_, HID_, 3 * HID_, 3 * HID_);

        // rope + split + cache scatter
        {
            dim3 grid(T_, NH_);
            rope_scatter<<<grid, 128>>>(qkv_, cosp, sinp, slots, q_, k_, v_,
                                        write_cache ? kc_base + (size_t)l * CACHE : nullptr,
                                        write_cache ? vc_base + (size_t)l * CACHE : nullptr);
        }

        // attention: scores = scale * Q @ K^T (causal tile skip)
        gemm_tf32<1><<<dim3(S_ / 128, S_ / 128, B_ * NH_), 256>>>(
            q_, k_, nullptr, scores_, HD_, HID_, HID_, S_);

        softmax_causal<<<B_ * NH_ * S_, 256>>>(scores_);

        // O = P @ V (causal K-limit)
        gemm_tf32<2><<<dim3(1, S_ / 128, B_ * NH_), 256>>>(
            scores_, v_, nullptr, o_, 0, S_, HID_, HID_);

        // dense projection
        gemm_tf32<0><<<dim3(HID_ / 128, T_ / 128), 256>>>(
            o_, dense_wl, nullptr, attn_, HID_, HID_, HID_, HID_);

        // post-attn norm
        rmsnorm_kernel<<<T_, 256>>>(attn_, res_, ln2_w + (size_t)l * HID_, norm_, res_);

        // MLP
        gemm_tf32<0><<<dim3(2 * INTER_ / 128, T_ / 128), 256>>>(
            norm_, gateup_wl, nullptr, gu_, HID_, HID_, 2 * INTER_, 2 * INTER_);

        silu_mul<<<(T_ * INTER_) / 256, 256>>>(gu_, act_);

        gemm_tf32<0><<<dim3(HID_ / 128, T_ / 128), 256>>>(
            act_, down_wl, nullptr, h_, INTER_, INTER_, HID_, HID_);
    }

    // final norm -> out
    rmsnorm_kernel<<<T_, 256>>>(h_, res_, final_ln_w, out, nullptr);
}

// round 6
// speedup vs baseline: 2.2772x; 1.6861x over previous
#include <cuda_runtime.h>
#include <cuda_fp16.h>
#include <math.h>
#include <stdint.h>

// ---------------- model constants ----------------
#define L_     2
#define HID_   4096
#define NH_    32
#define HD_    128
#define INTER_ 13696
#define B_     2
#define S_     1024
#define T_     2048
#define NBLK_  160
#define BLK_   16
#define ROT_   64
#define NFREQ_ 32
#define EPS_   1e-5f
#define SCALE_ 0.08838834764831845f

// ---------------- scratch ----------------
#define OFF_H      ((size_t)0)
#define OFF_RES    ((size_t)8388608)
#define OFF_NORM   ((size_t)16777216)
#define OFF_Q      ((size_t)25165824)
#define OFF_K      ((size_t)33554432)
#define OFF_V      ((size_t)41943040)
#define OFF_O      ((size_t)50331648)
#define OFF_ATTN   ((size_t)58720256)
#define OFF_QKV    ((size_t)67108864)
#define OFF_SCORES ((size_t)92274688)
#define OFF_GU     ((size_t)159383552)
#define OFF_ACT    ((size_t)215482368)
#define SCRATCH_TOTAL ((size_t)243531776)

__device__ float g_scratch[SCRATCH_TOTAL];

// split x into fp16 hi + fp16 lo (residual); pack two consecutive-k elements
// into one u32 (even k in low half).
__device__ __forceinline__ void split2_f16(float x0, float x1,
                                           uint32_t& hi, uint32_t& lo) {
    __half h0 = __float2half_rn(x0);
    __half h1 = __float2half_rn(x1);
    __half l0 = __float2half_rn(x0 - __half2float(h0));
    __half l1 = __float2half_rn(x1 - __half2float(h1));
    hi = (uint32_t)__half_as_ushort(h0) | ((uint32_t)__half_as_ushort(h1) << 16);
    lo = (uint32_t)__half_as_ushort(l0) | ((uint32_t)__half_as_ushort(l1) << 16);
}

// ---------------- embedding gather ----------------
__global__ void embed_kernel(const int* __restrict__ ids,
                             const float* __restrict__ E,
                             float* __restrict__ h) {
    int t = blockIdx.x;
    int id = ids[t];
    const float* er = E + (size_t)id * HID_;
    float* hr = h + (size_t)t * HID_;
    for (int i = threadIdx.x; i < HID_; i += 256) hr[i] = er[i];
}

// ---------------- fused (residual-add) RMSNorm ----------------
__global__ void rmsnorm_kernel(const float* __restrict__ x,
                               const float* __restrict__ resin,
                               const float* __restrict__ w,
                               float* __restrict__ outn,
                               float* __restrict__ resout) {
    int t = blockIdx.x, tid = threadIdx.x;
    const float* xr = x + (size_t)t * HID_;
    const float* rr = resin ? resin + (size_t)t * HID_ : nullptr;
    float* on = outn + (size_t)t * HID_;
    float* ro = resout ? resout + (size_t)t * HID_ : nullptr;

    float v[16];
    float ss = 0.f;
#pragma unroll
    for (int i = 0; i < 16; i++) {
        int c = tid + i * 256;
        float a = xr[c];
        if (rr) a += rr[c];
        v[i] = a;
        ss += a * a;
    }
    __shared__ float red[8];
#pragma unroll
    for (int o = 16; o; o >>= 1) ss += __shfl_xor_sync(0xffffffffu, ss, o);
    if ((tid & 31) == 0) red[tid >> 5] = ss;
    __syncthreads();
    float tot = 0.f;
#pragma unroll
    for (int i = 0; i < 8; i++) tot += red[i];
    float inv = rsqrtf(tot * (1.0f / HID_) + EPS_);
#pragma unroll
    for (int i = 0; i < 16; i++) {
        int c = tid + i * 256;
        if (ro) ro[c] = v[i];
        on[c] = w[c] * v[i] * inv;
    }
}

// ============================================================
// FP16x3 tensor-core GEMM (error-compensated; ~tf32x3 accuracy,
// 2x FLOP/instr vs tf32 path). 128x128 CTA tile, k-tile 16,
// 8 warps x (64x32) via 4x4 m16n8k16 mma.sync.
// SMEM holds pre-split fp16 hi/lo pairs (split once at fill).
// 3 mma passes: a_hi*b_lo + a_lo*b_hi + a_hi*b_hi.
//
// MODE 0: C = A(row, lda) @ B(row[k][n], ldb) [+bias].
// MODE 1: scores = scale * Q @ K^T per (b,h); causal tile skip.
// MODE 2: PV per (b,h) with causal K-limit = (by+1)*128.
// ============================================================
template<int MODE>
__global__ void __launch_bounds__(256) gemm_f16(
    const float* __restrict__ Ag, const float* __restrict__ Bg,
    const float* __restrict__ bias, float* __restrict__ Cg,
    int K, int lda, int ldb, int ldc)
{
    int bx = blockIdx.x, by = blockIdx.y, bz = blockIdx.z;
    const float* A = Ag;
    const float* B = Bg;
    float* C = Cg;
    if (MODE == 1) {
        if (bx > by) return;
        int b = bz >> 5, h = bz & 31;
        A += ((size_t)b * S_) * lda + h * HD_;
        B += ((size_t)b * S_) * ldb + h * HD_;
        C += (size_t)bz * S_ * S_;
        K = HD_;
    } else if (MODE == 2) {
        int b = bz >> 5, h = bz & 31;
        A += (size_t)bz * S_ * S_;
        B += ((size_t)b * S_) * ldb + h * HD_;
        C += ((size_t)b * S_) * ldc + h * HD_;
        K = (by + 1) * 128;
    }

    // A tiles: [128 m][16 k] fp16, row stride 48B (24 halves) -> 6144B.
    // B tiles MODE 1: same layout as A ([n][k]).
    // B tiles MODE 0/2: paired [8 k-pair][128 n] u32, row stride 544B.
    __shared__ uint8_t AsH[2][6144], AsL[2][6144];
    __shared__ uint8_t BsH[2][6144], BsL[2][6144];

    int tid = threadIdx.x;
    int lane = tid & 31, warp = tid >> 5;
    int g = lane >> 2, tg = lane & 3;
    int wm = (warp & 1) * 64;
    int wn = (warp >> 1) * 32;

    // fill mapping
    int ar = tid >> 1;            // 0..127
    int ak = (tid & 1) * 8;       // 0 or 8
    const float* Aptr = A + (size_t)(by * 128 + ar) * lda + ak;

    const float* Bptr0;
    const float* Bptr1 = nullptr;
    int pk = 0, nq = 0;
    if (MODE == 1) {
        Bptr0 = B + (size_t)(bx * 128 + ar) * ldb + ak;
    } else {
        pk = tid >> 5;            // 0..7 (k-pair row)
        nq = (tid & 31) * 4;      // 0..124
        Bptr0 = B + (size_t)(2 * pk) * ldb + bx * 128 + nq;
        Bptr1 = Bptr0 + ldb;
    }

    float4 pa0, pa1, pb0, pb1;

    auto ldg_tile = [&](int k0) {
        pa0 = *(const float4*)(Aptr + k0);
        pa1 = *(const float4*)(Aptr + k0 + 4);
        if (MODE == 1) {
            pb0 = *(const float4*)(Bptr0 + k0);
            pb1 = *(const float4*)(Bptr0 + k0 + 4);
        } else {
            pb0 = *(const float4*)(Bptr0 + (size_t)k0 * ldb);
            pb1 = *(const float4*)(Bptr1 + (size_t)k0 * ldb);
        }
    };

    auto sts_tile = [&](int buf) {
        uint32_t h0, l0, h1, l1, h2, l2, h3, l3;
        split2_f16(pa0.x, pa0.y, h0, l0);
        split2_f16(pa0.z, pa0.w, h1, l1);
        split2_f16(pa1.x, pa1.y, h2, l2);
        split2_f16(pa1.z, pa1.w, h3, l3);
        *(uint4*)(AsH[buf] + ar * 48 + ak * 2) = make_uint4(h0, h1, h2, h3);
        *(uint4*)(AsL[buf] + ar * 48 + ak * 2) = make_uint4(l0, l1, l2, l3);
        if (MODE == 1) {
            split2_f16(pb0.x, pb0.y, h0, l0);
            split2_f16(pb0.z, pb0.w, h1, l1);
            split2_f16(pb1.x, pb1.y, h2, l2);
            split2_f16(pb1.z, pb1.w, h3, l3);
            *(uint4*)(BsH[buf] + ar * 48 + ak * 2) = make_uint4(h0, h1, h2, h3);
            *(uint4*)(BsL[buf] + ar * 48 + ak * 2) = make_uint4(l0, l1, l2, l3);
        } else {
            // pack (k=2pk) into low half, (k=2pk+1) into high half
            split2_f16(pb0.x, pb1.x, h0, l0);
            split2_f16(pb0.y, pb1.y, h1, l1);
            split2_f16(pb0.z, pb1.z, h2, l2);
            split2_f16(pb0.w, pb1.w, h3, l3);
            *(uint4*)(BsH[buf] + pk * 544 + nq * 4) = make_uint4(h0, h1, h2, h3);
            *(uint4*)(BsL[buf] + pk * 544 + nq * 4) = make_uint4(l0, l1, l2, l3);
        }
    };

    float acc[4][4][4] = {};

#define MMA_F16(ACC, A0, A1, A2, A3, B0, B1)                                   \
    asm volatile(                                                              \
        "mma.sync.aligned.m16n8k16.row.col.f32.f16.f16.f32 "                   \
        "{%0,%1,%2,%3}, {%4,%5,%6,%7}, {%8,%9}, {%0,%1,%2,%3};"                \
        : "+f"((ACC)[0]), "+f"((ACC)[1]), "+f"((ACC)[2]), "+f"((ACC)[3])       \
        : "r"(A0), "r"(A1), "r"(A2), "r"(A3), "r"(B0), "r"(B1))

    auto compute = [&](int buf) {
        uint32_t ah[4][4], al[4][4], bh[4][2], bl[4][2];
#pragma unroll
        for (int mt = 0; mt < 4; mt++) {
            int m = wm + mt * 16 + g;
            const uint8_t* pH = AsH[buf] + m * 48 + tg * 4;
            const uint8_t* pL = AsL[buf] + m * 48 + tg * 4;
            ah[mt][0] = *(const uint32_t*)(pH);
            ah[mt][1] = *(const uint32_t*)(pH + 8 * 48);
            ah[mt][2] = *(const uint32_t*)(pH + 16);
            ah[mt][3] = *(const uint32_t*)(pH + 8 * 48 + 16);
            al[mt][0] = *(const uint32_t*)(pL);
            al[mt][1] = *(const uint32_t*)(pL + 8 * 48);
            al[mt][2] = *(const uint32_t*)(pL + 16);
            al[mt][3] = *(const uint32_t*)(pL + 8 * 48 + 16);
        }
#pragma unroll
        for (int nt = 0; nt < 4; nt++) {
            int n = wn + nt * 8 + g;
            if (MODE == 1) {
                const uint8_t* pH = BsH[buf] + n * 48 + tg * 4;
                const uint8_t* pL = BsL[buf] + n * 48 + tg * 4;
                bh[nt][0] = *(const uint32_t*)(pH);
                bh[nt][1] = *(const uint32_t*)(pH + 16);
                bl[nt][0] = *(const uint32_t*)(pL);
                bl[nt][1] = *(const uint32_t*)(pL + 16);
            } else {
                const uint8_t* pH = BsH[buf] + tg * 544 + n * 4;
                const uint8_t* pL = BsL[buf] + tg * 544 + n * 4;
                bh[nt][0] = *(const uint32_t*)(pH);
                bh[nt][1] = *(const uint32_t*)(pH + 4 * 544);
                bl[nt][0] = *(const uint32_t*)(pL);
                bl[nt][1] = *(const uint32_t*)(pL + 4 * 544);
            }
        }
#pragma unroll
        for (int mt = 0; mt < 4; mt++)
#pragma unroll
            for (int nt = 0; nt < 4; nt++) {
                MMA_F16(acc[mt][nt], ah[mt][0], ah[mt][1], ah[mt][2], ah[mt][3],
                        bl[nt][0], bl[nt][1]);
                MMA_F16(acc[mt][nt], al[mt][0], al[mt][1], al[mt][2], al[mt][3],
                        bh[nt][0], bh[nt][1]);
                MMA_F16(acc[mt][nt], ah[mt][0], ah[mt][1], ah[mt][2], ah[mt][3],
                        bh[nt][0], bh[nt][1]);
            }
    };

    int nk = K / 16;
    ldg_tile(0);
    sts_tile(0);
    __syncthreads();
    for (int kt = 0; kt < nk; kt++) {
        int buf = kt & 1;
        if (kt + 1 < nk) ldg_tile((kt + 1) * 16);
        compute(buf);
        if (kt + 1 < nk) sts_tile(buf ^ 1);
        __syncthreads();
    }

    // ---- epilogue ----
#pragma unroll
    for (int mt = 0; mt < 4; mt++) {
#pragma unroll
        for (int i = 0; i < 2; i++) {
            int r = by * 128 + wm + mt * 16 + g + i * 8;
#pragma unroll
            for (int nt = 0; nt < 4; nt++) {
                int c = bx * 128 + wn + nt * 8 + 2 * tg;
                float v0 = acc[mt][nt][i * 2 + 0];
                float v1 = acc[mt][nt][i * 2 + 1];
                if (MODE == 0 && bias) {
                    v0 += bias[c];
                    v1 += bias[c + 1];
                }
                if (MODE == 1) {
                    v0 *= SCALE_;
                    v1 *= SCALE_;
                }
                *(float2*)&C[(size_t)r * ldc + c] = make_float2(v0, v1);
            }
        }
    }
}

// ---------------- rope + split + KV-cache scatter ----------------
__global__ void rope_scatter(const float* __restrict__ qkv,
                             const float* __restrict__ cosp,
                             const float* __restrict__ sinp,
                             const int* __restrict__ slots,
                             float* __restrict__ q, float* __restrict__ k,
                             float* __restrict__ v,
                             float* __restrict__ kc, float* __restrict__ vc) {
    int t = blockIdx.x, h = blockIdx.y, d = threadIdx.x;
    const float* row = qkv + (size_t)t * (3 * HID_);
    float qv, kv;
    if (d < ROT_) {
        int f = d >> 1;
        float c = cosp[t * NFREQ_ + f];
        float s = sinp[t * NFREQ_ + f];
        float q0 = row[h * HD_ + f * 2];
        float q1 = row[h * HD_ + f * 2 + 1];
        float k0 = row[HID_ + h * HD_ + f * 2];
        float k1 = row[HID_ + h * HD_ + f * 2 + 1];
        if (d & 1) { qv = q1 * c + q0 * s; kv = k1 * c + k0 * s; }
        else       { qv = q0 * c - q1 * s; kv = k0 * c - k1 * s; }
    } else {
        qv = row[h * HD_ + d];
        kv = row[HID_ + h * HD_ + d];
    }
    float vv = row[2 * HID_ + h * HD_ + d];
    size_t o = (size_t)t * HID_ + h * HD_ + d;
    q[o] = qv; k[o] = kv; v[o] = vv;
    if (kc) {
        int slot = slots[t];
        size_t co = ((size_t)slot * NH_ + h) * HD_ + d;
        kc[co] = kv; vc[co] = vv;
    }
}

// ---------------- causal softmax (zero-fills above diagonal) ----------------
__global__ void softmax_causal(float* __restrict__ Sc) {
    int row = blockIdx.x;
    int qi = row & (S_ - 1);
    float* sr = Sc + (size_t)row * S_;
    int n = qi + 1;
    int tid = threadIdx.x;
    __shared__ float red[8];

    float m = -1e30f;
    for (int k = tid; k < n; k += 256) m = fmaxf(m, sr[k]);
#pragma unroll
    for (int o = 16; o; o >>= 1) m = fmaxf(m, __shfl_xor_sync(0xffffffffu, m, o));
    if ((tid & 31) == 0) red[tid >> 5] = m;
    __syncthreads();
    float mm = red[0];
#pragma unroll
    for (int i = 1; i < 8; i++) mm = fmaxf(mm, red[i]);
    __syncthreads();

    float sum = 0.f;
    for (int k = tid; k < n; k += 256) {
        float e = expf(sr[k] - mm);
        sr[k] = e;
        sum += e;
    }
#pragma unroll
    for (int o = 16; o; o >>= 1) sum += __shfl_xor_sync(0xffffffffu, sum, o);
    if ((tid & 31) == 0) red[tid >> 5] = sum;
    __syncthreads();
    float tot = 0.f;
#pragma unroll
    for (int i = 0; i < 8; i++) tot += red[i];
    float inv = 1.f / tot;
    for (int k = tid; k < n; k += 256) sr[k] *= inv;
    for (int k = n + tid; k < S_; k += 256) sr[k] = 0.f;
}

// ---------------- silu(gate) * up ----------------
__global__ void silu_mul(const float* __restrict__ gu, float* __restrict__ act) {
    size_t idx = (size_t)blockIdx.x * 256 + threadIdx.x;
    size_t t = idx / INTER_;
    size_t i = idx - t * INTER_;
    const float* row = gu + t * (2 * INTER_);
    float g = row[i];
    float u = row[INTER_ + i];
    act[idx] = (g / (1.f + expf(-g))) * u;
}

// ---------------- host orchestration ----------------
extern "C" void kernel_launch(void* const* d_in, const int* in_sizes, int n_in,
                              void* d_out, int out_size) {
    const int* input_ids = (const int*)d_in[0];
    const float* cosp = (const float*)d_in[1];
    const float* sinp = (const float*)d_in[2];
    const int* slots = (const int*)d_in[3];
    const float* embed = (const float*)d_in[6];
    const float* qkv_w = (const float*)d_in[7];
    const float* qkv_b = (const float*)d_in[8];
    const float* dense_w = (const float*)d_in[9];
    const float* gateup_w = (const float*)d_in[10];
    const float* down_w = (const float*)d_in[11];
    const float* ln1_w = (const float*)d_in[12];
    const float* ln2_w = (const float*)d_in[13];
    const float* final_ln_w = (const float*)d_in[14];

    float* out = (float*)d_out;

    float* scratch = nullptr;
    cudaGetSymbolAddress((void**)&scratch, g_scratch);
    float* h_ = scratch + OFF_H;
    float* res_ = scratch + OFF_RES;
    float* norm_ = scratch + OFF_NORM;
    float* q_ = scratch + OFF_Q;
    float* k_ = scratch + OFF_K;
    float* v_ = scratch + OFF_V;
    float* o_ = scratch + OFF_O;
    float* attn_ = scratch + OFF_ATTN;
    float* qkv_ = scratch + OFF_QKV;
    float* scores_ = scratch + OFF_SCORES;
    float* gu_ = scratch + OFF_GU;
    float* act_ = scratch + OFF_ACT;

    const size_t CACHE = (size_t)NBLK_ * BLK_ * NH_ * HD_;
    float* kc_base = out + (size_t)T_ * HID_;
    float* vc_base = kc_base + (size_t)L_ * CACHE;
    bool write_cache =
        (size_t)out_size >= (size_t)T_ * HID_ + 2 * (size_t)L_ * CACHE;
    if (write_cache) {
        cudaMemsetAsync(kc_base, 0, 2 * (size_t)L_ * CACHE * sizeof(float), 0);
    }

    embed_kernel<<<T_, 256>>>(input_ids, embed, h_);

    for (int l = 0; l < L_; l++) {
        const float* qkv_wl = qkv_w + (size_t)l * HID_ * 3 * HID_;
        const float* qkv_bl = qkv_b + (size_t)l * 3 * HID_;
        const float* dense_wl = dense_w + (size_t)l * HID_ * HID_;
        const float* gateup_wl = gateup_w + (size_t)l * HID_ * 2 * INTER_;
        const float* down_wl = down_w + (size_t)l * INTER_ * HID_;

        rmsnorm_kernel<<<T_, 256>>>(h_, (l == 0) ? nullptr : res_,
                                    ln1_w + (size_t)l * HID_, norm_, res_);

        gemm_f16<0><<<dim3(3 * HID_ / 128, T_ / 128), 256>>>(
            norm_, qkv_wl, qkv_bl, qkv_, HID_, HID_, 3 * HID_, 3 * HID_);

        {
            dim3 grid(T_, NH_);
            rope_scatter<<<grid, 128>>>(qkv_, cosp, sinp, slots, q_, k_, v_,
                                        write_cache ? kc_base + (size_t)l * CACHE : nullptr,
                                        write_cache ? vc_base + (size_t)l * CACHE : nullptr);
        }

        gemm_f16<1><<<dim3(S_ / 128, S_ / 128, B_ * NH_), 256>>>(
            q_, k_, nullptr, scores_, HD_, HID_, HID_, S_);

        softmax_causal<<<B_ * NH_ * S_, 256>>>(scores_);

        gemm_f16<2><<<dim3(1, S_ / 128, B_ * NH_), 256>>>(
            scores_, v_, nullptr, o_, 0, S_, HID_, HID_);

        gemm_f16<0><<<dim3(HID_ / 128, T_ / 128), 256>>>(
            o_, dense_wl, nullptr, attn_, HID_, HID_, HID_, HID_);

        rmsnorm_kernel<<<T_, 256>>>(attn_, res_, ln2_w + (size_t)l * HID_, norm_, res_);

        gemm_f16<0><<<dim3(2 * INTER_ / 128, T_ / 128), 256>>>(
            norm_, gateup_wl, nullptr, gu_, HID_, HID_, 2 * INTER_, 2 * INTER_);

        silu_mul<<<(T_ * INTER_) / 256, 256>>>(gu_, act_);

        gemm_f16<0><<<dim3(HID_ / 128, T_ / 128), 256>>>(
            act_, down_wl, nullptr, h_, INTER_, INTER_, HID_, HID_);
    }

    rmsnorm_kernel<<<T_, 256>>>(h_, res_, final_ln_w, out, nullptr);
}